// round 7
// baseline (speedup 1.0000x reference)
#include <cuda_runtime.h>
#include <math.h>
#include <stdint.h>

#define NN 100000
#define EE 1600000
#define FF 512
#define HH 256

// ---------------- scratch (static device globals; no allocation) ------------
__device__ float g_B0[(size_t)NN * HH];
__device__ float g_B1[(size_t)NN * HH];
__device__ float g_B2[(size_t)NN * HH];
__device__ int   g_odeg[NN];
__device__ int   g_ideg[NN];
__device__ float g_nsrc[NN];
__device__ float g_ndst[NN];
__device__ float g_psum[HH];
__device__ float g_pmax[HH];
// CSR (in-edges grouped by dst)
__device__ int   g_rowstart[NN + 1];
__device__ int   g_cursor[NN];
__device__ int   g_csr_src[EE];
__device__ int   g_blksum[512];

// ---------------- helpers ---------------------------------------------------
__device__ __forceinline__ void atomicMaxFloat(float* addr, float v) {
    if (v >= 0.0f) atomicMax((int*)addr, __float_as_int(v));
    else           atomicMin((unsigned int*)addr, __float_as_uint(v));
}

__device__ __forceinline__ float leaky(float x) {
    return x > 0.0f ? x : 0.01f * x;
}

__device__ __forceinline__ float4 f4add(float4 a, float4 b) {
    return make_float4(a.x + b.x, a.y + b.y, a.z + b.z, a.w + b.w);
}

__device__ __forceinline__ uint32_t f2tf(float x) {
    uint32_t u;
    asm("cvt.rna.tf32.f32 %0, %1;" : "=r"(u) : "f"(x));
    return u;
}

__device__ __forceinline__ void mma_tf32(float* d, const uint32_t* a, const uint32_t* b) {
    asm volatile(
        "mma.sync.aligned.m16n8k8.row.col.f32.tf32.tf32.f32 "
        "{%0,%1,%2,%3}, {%4,%5,%6,%7}, {%8,%9}, {%0,%1,%2,%3};\n"
        : "+f"(d[0]), "+f"(d[1]), "+f"(d[2]), "+f"(d[3])
        : "r"(a[0]), "r"(a[1]), "r"(a[2]), "r"(a[3]), "r"(b[0]), "r"(b[1]));
}

// ---------------- small kernels ---------------------------------------------
__global__ void k_prep() {
    int i = blockIdx.x * blockDim.x + threadIdx.x;
    if (i < NN) {
        g_odeg[i] = 0;
        g_ideg[i] = 0;
    }
}

__global__ void k_degree(const int* __restrict__ src, const int* __restrict__ dst) {
    int e = blockIdx.x * blockDim.x + threadIdx.x;
    if (e < EE) {
        atomicAdd(&g_odeg[src[e]], 1);
        atomicAdd(&g_ideg[dst[e]], 1);
    }
}

__global__ void k_norm() {
    int i = blockIdx.x * blockDim.x + threadIdx.x;
    if (i < NN) {
        g_nsrc[i] = rsqrtf(fmaxf((float)g_odeg[i], 1.0f));
        g_ndst[i] = rsqrtf(fmaxf((float)g_ideg[i], 1.0f));
    }
    if (blockIdx.x == 0 && threadIdx.x < HH) {
        g_psum[threadIdx.x] = 0.0f;
        g_pmax[threadIdx.x] = -INFINITY;
    }
}

// ---------------- CSR build ---------------------------------------------------
__global__ void k_scan1() {
    __shared__ int sh[256];
    int t = threadIdx.x;
    int i = blockIdx.x * 256 + t;
    int v = (i < NN) ? g_ideg[i] : 0;
    sh[t] = v;
    __syncthreads();
    #pragma unroll
    for (int off = 1; off < 256; off <<= 1) {
        int add = (t >= off) ? sh[t - off] : 0;
        __syncthreads();
        sh[t] += add;
        __syncthreads();
    }
    if (i < NN) g_rowstart[i] = sh[t] - v;
    if (t == 255) g_blksum[blockIdx.x] = sh[255];
}

__global__ void k_scan2(int nblk) {
    __shared__ int sh[512];
    int t = threadIdx.x;
    int v = (t < nblk) ? g_blksum[t] : 0;
    sh[t] = v;
    __syncthreads();
    #pragma unroll
    for (int off = 1; off < 512; off <<= 1) {
        int add = (t >= off) ? sh[t - off] : 0;
        __syncthreads();
        sh[t] += add;
        __syncthreads();
    }
    if (t < nblk) g_blksum[t] = sh[t] - v;
}

__global__ void k_scan3() {
    int i = blockIdx.x * blockDim.x + threadIdx.x;
    if (i < NN) {
        g_rowstart[i] += g_blksum[i >> 8];
        g_cursor[i] = 0;
    }
    if (i == 0) g_rowstart[NN] = EE;
}

__global__ void k_csr_fill(const int* __restrict__ src, const int* __restrict__ dst) {
    int e = blockIdx.x * blockDim.x + threadIdx.x;
    if (e < EE) {
        int d = dst[e];
        int pos = atomicAdd(&g_cursor[d], 1);
        g_csr_src[g_rowstart[d] + pos] = src[e];
    }
}

// ---------------- tensor-core GEMM (3xTF32) ----------------------------------
template <int K>
__global__ void __launch_bounds__(256, 2)
k_gemm_tc(const float* __restrict__ A, const float* __restrict__ W,
          const float* __restrict__ norm, float* __restrict__ C) {
    __shared__ uint32_t Ah[16][132];
    __shared__ uint32_t Al[16][132];
    __shared__ uint32_t Bh[16][132];
    __shared__ uint32_t Bl[16][132];

    const int tid  = threadIdx.x;
    const int lane = tid & 31;
    const int wid  = tid >> 5;
    const int wm   = wid >> 1;
    const int wn   = wid & 1;
    const int m0   = blockIdx.y * 128;
    const int n0   = blockIdx.x * 128;

    const int a_r0 = tid >> 2;
    const int a_r1 = a_r0 + 64;
    const int a_c  = (tid & 3) << 2;
    const int b_r0 = tid >> 5;
    const int b_r1 = b_r0 + 8;
    const int b_c  = (tid & 31) << 2;

    const float nrm0 = (m0 + a_r0 < NN) ? norm[m0 + a_r0] : 0.f;
    const float nrm1 = (m0 + a_r1 < NN) ? norm[m0 + a_r1] : 0.f;

    float acc[2][8][4];
    #pragma unroll
    for (int mt = 0; mt < 2; mt++)
        #pragma unroll
        for (int nt = 0; nt < 8; nt++)
            #pragma unroll
            for (int i = 0; i < 4; i++) acc[mt][nt][i] = 0.f;

    float4 pa0, pa1, pb0, pb1;

    #define LOAD_TILE(kt)                                                        \
        {                                                                        \
            int kbase = (kt) * 16;                                               \
            pa0 = (m0 + a_r0 < NN)                                               \
                ? *(const float4*)(A + (size_t)(m0 + a_r0) * K + kbase + a_c)    \
                : make_float4(0.f, 0.f, 0.f, 0.f);                               \
            pa1 = (m0 + a_r1 < NN)                                               \
                ? *(const float4*)(A + (size_t)(m0 + a_r1) * K + kbase + a_c)    \
                : make_float4(0.f, 0.f, 0.f, 0.f);                               \
            pb0 = *(const float4*)(W + (size_t)(kbase + b_r0) * HH + n0 + b_c);  \
            pb1 = *(const float4*)(W + (size_t)(kbase + b_r1) * HH + n0 + b_c);  \
        }

    #define STORE_TILE()                                                         \
        {                                                                        \
            float av[8] = {pa0.x * nrm0, pa0.y * nrm0, pa0.z * nrm0,             \
                           pa0.w * nrm0, pa1.x * nrm1, pa1.y * nrm1,             \
                           pa1.z * nrm1, pa1.w * nrm1};                          \
            _Pragma("unroll")                                                    \
            for (int j = 0; j < 4; j++) {                                        \
                uint32_t h0 = f2tf(av[j]);                                       \
                Ah[a_c + j][a_r0] = h0;                                          \
                Al[a_c + j][a_r0] = f2tf(av[j] - __uint_as_float(h0));           \
                uint32_t h1 = f2tf(av[4 + j]);                                   \
                Ah[a_c + j][a_r1] = h1;                                          \
                Al[a_c + j][a_r1] = f2tf(av[4 + j] - __uint_as_float(h1));       \
            }                                                                    \
            float bv[8] = {pb0.x, pb0.y, pb0.z, pb0.w, pb1.x, pb1.y, pb1.z, pb1.w}; \
            _Pragma("unroll")                                                    \
            for (int j = 0; j < 4; j++) {                                        \
                uint32_t h0 = f2tf(bv[j]);                                       \
                Bh[b_r0][b_c + j] = h0;                                          \
                Bl[b_r0][b_c + j] = f2tf(bv[j] - __uint_as_float(h0));           \
                uint32_t h1 = f2tf(bv[4 + j]);                                   \
                Bh[b_r1][b_c + j] = h1;                                          \
                Bl[b_r1][b_c + j] = f2tf(bv[4 + j] - __uint_as_float(h1));       \
            }                                                                    \
        }

    constexpr int KT = K / 16;

    LOAD_TILE(0);
    STORE_TILE();
    __syncthreads();

    for (int kt = 0; kt < KT; kt++) {
        if (kt + 1 < KT) LOAD_TILE(kt + 1);

        #pragma unroll
        for (int kk = 0; kk < 2; kk++) {
            const int colA = kk * 8 + (lane & 3);
            const int rowA = wm * 32 + (lane >> 2);
            const int rowB = kk * 8 + (lane & 3);
            const int colB = wn * 64 + (lane >> 2);

            uint32_t ah[2][4];
            #pragma unroll
            for (int mt = 0; mt < 2; mt++) {
                int r = rowA + mt * 16;
                ah[mt][0] = Ah[colA][r];
                ah[mt][1] = Ah[colA][r + 8];
                ah[mt][2] = Ah[colA + 4][r];
                ah[mt][3] = Ah[colA + 4][r + 8];
            }
            uint32_t bh[8][2];
            #pragma unroll
            for (int nt = 0; nt < 8; nt++) {
                bh[nt][0] = Bh[rowB][colB + nt * 8];
                bh[nt][1] = Bh[rowB + 4][colB + nt * 8];
            }
            #pragma unroll
            for (int mt = 0; mt < 2; mt++)
                #pragma unroll
                for (int nt = 0; nt < 8; nt++)
                    mma_tf32(acc[mt][nt], ah[mt], bh[nt]);

            uint32_t bl[8][2];
            #pragma unroll
            for (int nt = 0; nt < 8; nt++) {
                bl[nt][0] = Bl[rowB][colB + nt * 8];
                bl[nt][1] = Bl[rowB + 4][colB + nt * 8];
            }
            #pragma unroll
            for (int mt = 0; mt < 2; mt++)
                #pragma unroll
                for (int nt = 0; nt < 8; nt++)
                    mma_tf32(acc[mt][nt], ah[mt], bl[nt]);

            uint32_t al[2][4];
            #pragma unroll
            for (int mt = 0; mt < 2; mt++) {
                int r = rowA + mt * 16;
                al[mt][0] = Al[colA][r];
                al[mt][1] = Al[colA][r + 8];
                al[mt][2] = Al[colA + 4][r];
                al[mt][3] = Al[colA + 4][r + 8];
            }
            #pragma unroll
            for (int mt = 0; mt < 2; mt++)
                #pragma unroll
                for (int nt = 0; nt < 8; nt++)
                    mma_tf32(acc[mt][nt], al[mt], bh[nt]);
        }

        __syncthreads();
        if (kt + 1 < KT) {
            STORE_TILE();
            __syncthreads();
        }
    }

    #pragma unroll
    for (int mt = 0; mt < 2; mt++) {
        #pragma unroll
        for (int nt = 0; nt < 8; nt++) {
            int row = m0 + wm * 32 + mt * 16 + (lane >> 2);
            int col = n0 + wn * 64 + nt * 8 + (lane & 3) * 2;
            if (row < NN)
                *(float2*)(C + (size_t)row * HH + col) =
                    make_float2(acc[mt][nt][0], acc[mt][nt][1]);
            if (row + 8 < NN)
                *(float2*)(C + (size_t)(row + 8) * HH + col) =
                    make_float2(acc[mt][nt][2], acc[mt][nt][3]);
        }
    }
    #undef LOAD_TILE
    #undef STORE_TILE
}

// ---------------- CSR gather: smem-staged indices, 4-edge unrolled ----------
// O[n] = leaky( (sum_{e in in(n)} X[src[e]]) * ndst[n] + bias )
// One warp per node. Indices burst-loaded (coalesced) into smem, consumed via
// LDS so the L2 round-trip for indices is off the row-load critical path.
template <bool POOL>
__global__ void __launch_bounds__(256)
k_gather(const float4* __restrict__ X, float4* __restrict__ O,
         const float* __restrict__ ndst, const float* __restrict__ bias) {
    __shared__ int   s_idx[8][128];
    __shared__ float s_sum[HH];
    __shared__ float s_max[HH];

    const int lane = threadIdx.x & 31;
    const int wip  = threadIdx.x >> 5;            // warp in block
    const int n    = (blockIdx.x * blockDim.x + threadIdx.x) >> 5;

    if (POOL) {
        s_sum[threadIdx.x] = 0.0f;
        s_max[threadIdx.x] = -INFINITY;
        __syncthreads();
    }

    float4 o0, o1;
    const bool valid = (n < NN);
    if (valid) {
        const int beg = g_rowstart[n];
        const int cnt = g_rowstart[n + 1] - beg;
        float4 a0 = make_float4(0.f, 0.f, 0.f, 0.f);
        float4 a1 = make_float4(0.f, 0.f, 0.f, 0.f);

        for (int base = 0; base < cnt; base += 128) {
            const int chunk = min(128, cnt - base);
            // coalesced burst load of indices into smem
            for (int j = lane; j < chunk; j += 32)
                s_idx[wip][j] = __ldg(&g_csr_src[beg + base + j]);
            __syncwarp();

            int j = 0;
            for (; j + 4 <= chunk; j += 4) {
                int s0 = s_idx[wip][j + 0];
                int s1 = s_idx[wip][j + 1];
                int s2 = s_idx[wip][j + 2];
                int s3 = s_idx[wip][j + 3];
                const float4* x0 = X + (size_t)s0 * (HH / 4);
                const float4* x1 = X + (size_t)s1 * (HH / 4);
                const float4* x2 = X + (size_t)s2 * (HH / 4);
                const float4* x3 = X + (size_t)s3 * (HH / 4);
                float4 v00 = x0[lane];      float4 v01 = x0[lane + 32];
                float4 v10 = x1[lane];      float4 v11 = x1[lane + 32];
                float4 v20 = x2[lane];      float4 v21 = x2[lane + 32];
                float4 v30 = x3[lane];      float4 v31 = x3[lane + 32];
                a0 = f4add(a0, f4add(f4add(v00, v10), f4add(v20, v30)));
                a1 = f4add(a1, f4add(f4add(v01, v11), f4add(v21, v31)));
            }
            for (; j < chunk; j++) {
                int s = s_idx[wip][j];
                const float4* xs = X + (size_t)s * (HH / 4);
                a0 = f4add(a0, xs[lane]);
                a1 = f4add(a1, xs[lane + 32]);
            }
            __syncwarp();
        }

        const float nd = ndst[n];
        float4 bb0 = ((const float4*)bias)[lane];
        float4 bb1 = ((const float4*)bias)[lane + 32];
        o0.x = leaky(fmaf(a0.x, nd, bb0.x));
        o0.y = leaky(fmaf(a0.y, nd, bb0.y));
        o0.z = leaky(fmaf(a0.z, nd, bb0.z));
        o0.w = leaky(fmaf(a0.w, nd, bb0.w));
        o1.x = leaky(fmaf(a1.x, nd, bb1.x));
        o1.y = leaky(fmaf(a1.y, nd, bb1.y));
        o1.z = leaky(fmaf(a1.z, nd, bb1.z));
        o1.w = leaky(fmaf(a1.w, nd, bb1.w));

        if (POOL) {
            // output consumed only by k_final/pooling -> keep out of L2
            __stcs(&O[(size_t)n * (HH / 4) + lane], o0);
            __stcs(&O[(size_t)n * (HH / 4) + lane + 32], o1);
        } else {
            O[(size_t)n * (HH / 4) + lane]      = o0;
            O[(size_t)n * (HH / 4) + lane + 32] = o1;
        }
    }

    if (POOL) {
        if (valid) {
            const int c0 = lane * 4;
            const int c1 = 128 + lane * 4;
            atomicAdd(&s_sum[c0 + 0], o0.x); atomicAdd(&s_sum[c0 + 1], o0.y);
            atomicAdd(&s_sum[c0 + 2], o0.z); atomicAdd(&s_sum[c0 + 3], o0.w);
            atomicAdd(&s_sum[c1 + 0], o1.x); atomicAdd(&s_sum[c1 + 1], o1.y);
            atomicAdd(&s_sum[c1 + 2], o1.z); atomicAdd(&s_sum[c1 + 3], o1.w);
            atomicMaxFloat(&s_max[c0 + 0], o0.x); atomicMaxFloat(&s_max[c0 + 1], o0.y);
            atomicMaxFloat(&s_max[c0 + 2], o0.z); atomicMaxFloat(&s_max[c0 + 3], o0.w);
            atomicMaxFloat(&s_max[c1 + 0], o1.x); atomicMaxFloat(&s_max[c1 + 1], o1.y);
            atomicMaxFloat(&s_max[c1 + 2], o1.z); atomicMaxFloat(&s_max[c1 + 3], o1.w);
        }
        __syncthreads();
        atomicAdd(&g_psum[threadIdx.x], s_sum[threadIdx.x]);
        atomicMaxFloat(&g_pmax[threadIdx.x], s_max[threadIdx.x]);
    }
}

// ---------------- generator head ---------------------------------------------
__global__ void k_final(const float* __restrict__ B, const int* __restrict__ node_index,
                        const float* __restrict__ b2,
                        const float* __restrict__ Wg, const float* __restrict__ bg,
                        const float* __restrict__ eps, float* __restrict__ out) {
    __shared__ float pooled[768];
    __shared__ float red[256];
    int t  = threadIdx.x;
    int ni = *node_index;

    pooled[t]       = g_psum[t];
    pooled[256 + t] = g_pmax[t];
    pooled[512 + t] = B[(size_t)ni * HH + t];
    __syncthreads();

    float fdv[4];
    #pragma unroll
    for (int o = 0; o < 4; o++) {
        int k = t + o * 256;
        float acc = bg[k];
        for (int i = 0; i < 768; i++)
            acc = fmaf(pooled[i], Wg[(size_t)i * 1024 + k], acc);
        fdv[o] = acc;
    }
    float mu1 = fdv[0],        mu2 = fdv[1];
    float sg1 = fabsf(fdv[2]), sg2 = fabsf(fdv[3]);
    float e1 = eps[t], e2 = eps[t + 256];
    float fn1 = fmaf(sg1, e1, mu1);
    float fn2 = fmaf(sg2, e2, mu2);

    out[t]              = fn1;  out[t + 256]        = fn2;
    out[512 + t]        = mu1;  out[512 + t + 256]  = mu2;
    out[1024 + t]       = sg1;  out[1024 + t + 256] = sg2;

    const float HALF_LOG_2PI = 0.9189385332046727f;
    float r1 = (fn1 - mu1) / sg1;
    float r2 = (fn2 - mu2) / sg2;
    float lp = (-0.5f * r1 * r1 - logf(sg1) - HALF_LOG_2PI)
             + (-0.5f * r2 * r2 - logf(sg2) - HALF_LOG_2PI);
    red[t] = lp;
    __syncthreads();
    for (int off = 128; off > 0; off >>= 1) {
        if (t < off) red[t] += red[t + off];
        __syncthreads();
    }
    if (t == 0) out[1536] = red[0] / 512.0f;
}

// ---------------- launcher ----------------------------------------------------
extern "C" void kernel_launch(void* const* d_in, const int* in_sizes, int n_in,
                              void* d_out, int out_size) {
    const float* feat = (const float*)d_in[0];
    const int*   src  = (const int*)d_in[1];
    const int*   dst  = (const int*)d_in[2];
    const int*   nidx = (const int*)d_in[3];
    const float* W1   = (const float*)d_in[4];
    const float* b1   = (const float*)d_in[5];
    const float* W2   = (const float*)d_in[6];
    const float* b2   = (const float*)d_in[7];
    const float* Wg   = (const float*)d_in[8];
    const float* bg   = (const float*)d_in[9];
    const float* eps  = (const float*)d_in[10];
    float* out = (float*)d_out;

    void *p0, *p1, *p2, *pns, *pnd;
    cudaGetSymbolAddress(&p0, g_B0);
    cudaGetSymbolAddress(&p1, g_B1);
    cudaGetSymbolAddress(&p2, g_B2);
    cudaGetSymbolAddress(&pns, g_nsrc);
    cudaGetSymbolAddress(&pnd, g_ndst);
    float* B0 = (float*)p0;
    float* B1 = (float*)p1;
    float* B2 = (float*)p2;
    float* nsrc = (float*)pns;
    float* ndst = (float*)pnd;

    const int DEG_BLKS  = (EE + 255) / 256;
    const int N_BLKS    = (NN + 255) / 256;      // 391
    const dim3 GEMM_GRID(2, (NN + 127) / 128);   // 782 m-tiles x 2 n-tiles
    const int GATH_BLKS = (NN + 7) / 8;          // one warp per node

    // launch order chosen so stream index 3 (the ncu-profiled slot) is gemm1
    k_prep<<<N_BLKS, 256>>>();                                   // 0
    k_degree<<<DEG_BLKS, 256>>>(src, dst);                       // 1
    k_norm<<<N_BLKS, 256>>>();                                   // 2
    k_gemm_tc<FF><<<GEMM_GRID, 256>>>(feat, W1, nsrc, B0);       // 3  <- profiled
    k_scan1<<<N_BLKS, 256>>>();                                  // 4
    k_scan2<<<1, 512>>>(N_BLKS);                                 // 5
    k_scan3<<<N_BLKS, 256>>>();                                  // 6
    k_csr_fill<<<DEG_BLKS, 256>>>(src, dst);                     // 7
    k_gather<false><<<GATH_BLKS, 256>>>((const float4*)B0, (float4*)B1, ndst, b1); // 8
    k_gemm_tc<HH><<<GEMM_GRID, 256>>>(B1, W2, nsrc, B2);         // 9
    k_gather<true><<<GATH_BLKS, 256>>>((const float4*)B2, (float4*)B0, ndst, b2);  // 10
    k_final<<<1, 256>>>(B0, nidx, b2, Wg, bg, eps, out);         // 11
}

// round 9
// speedup vs baseline: 1.4239x; 1.4239x over previous
#include <cuda_runtime.h>
#include <math.h>
#include <stdint.h>

#define NN 100000
#define EE 1600000
#define FF 512
#define HH 256

// ---------------- scratch (static device globals; no allocation) ------------
__device__ float g_B0[(size_t)NN * HH];
__device__ float g_B1[(size_t)NN * HH];
__device__ float g_B2[(size_t)NN * HH];
__device__ int   g_odeg[NN];
__device__ int   g_ideg[NN];
__device__ float g_nsrc[NN];
__device__ float g_ndst[NN];
__device__ float g_psum[HH];
__device__ float g_pmax[HH];
// CSR (in-edges grouped by dst)
__device__ int   g_rowstart[NN + 1];
__device__ int   g_cursor[NN];
__device__ int   g_csr_src[EE];
__device__ int   g_blksum[512];

// ---------------- helpers ---------------------------------------------------
__device__ __forceinline__ void atomicMaxFloat(float* addr, float v) {
    if (v >= 0.0f) atomicMax((int*)addr, __float_as_int(v));
    else           atomicMin((unsigned int*)addr, __float_as_uint(v));
}

__device__ __forceinline__ float leaky(float x) {
    return x > 0.0f ? x : 0.01f * x;
}

__device__ __forceinline__ float4 f4add(float4 a, float4 b) {
    return make_float4(a.x + b.x, a.y + b.y, a.z + b.z, a.w + b.w);
}

__device__ __forceinline__ uint16_t f2bf(float x) {
    uint16_t r;
    asm("cvt.rn.bf16.f32 %0, %1;" : "=h"(r) : "f"(x));
    return r;
}
__device__ __forceinline__ float bf2f(uint16_t b) {
    return __uint_as_float(((uint32_t)b) << 16);
}
// pack two floats (x -> low half = k even, y -> high half = k odd) into
// bf16x2 hi part + bf16x2 lo (residual) part
__device__ __forceinline__ void bf16x3_pack(float x, float y, uint32_t& hi, uint32_t& lo) {
    uint16_t hx = f2bf(x);
    uint16_t hy = f2bf(y);
    uint16_t lx = f2bf(x - bf2f(hx));
    uint16_t ly = f2bf(y - bf2f(hy));
    hi = (uint32_t)hx | ((uint32_t)hy << 16);
    lo = (uint32_t)lx | ((uint32_t)ly << 16);
}

__device__ __forceinline__ void mma_bf16(float* d, const uint32_t* a, const uint32_t* b) {
    asm volatile(
        "mma.sync.aligned.m16n8k16.row.col.f32.bf16.bf16.f32 "
        "{%0,%1,%2,%3}, {%4,%5,%6,%7}, {%8,%9}, {%0,%1,%2,%3};\n"
        : "+f"(d[0]), "+f"(d[1]), "+f"(d[2]), "+f"(d[3])
        : "r"(a[0]), "r"(a[1]), "r"(a[2]), "r"(a[3]), "r"(b[0]), "r"(b[1]));
}

// ---------------- small kernels ---------------------------------------------
__global__ void k_prep() {
    int i = blockIdx.x * blockDim.x + threadIdx.x;
    if (i < NN) {
        g_odeg[i] = 0;
        g_ideg[i] = 0;
    }
}

__global__ void k_degree(const int* __restrict__ src, const int* __restrict__ dst) {
    int e = blockIdx.x * blockDim.x + threadIdx.x;
    if (e < EE) {
        atomicAdd(&g_odeg[src[e]], 1);
        atomicAdd(&g_ideg[dst[e]], 1);
    }
}

__global__ void k_norm() {
    int i = blockIdx.x * blockDim.x + threadIdx.x;
    if (i < NN) {
        g_nsrc[i] = rsqrtf(fmaxf((float)g_odeg[i], 1.0f));
        g_ndst[i] = rsqrtf(fmaxf((float)g_ideg[i], 1.0f));
    }
    if (blockIdx.x == 0 && threadIdx.x < HH) {
        g_psum[threadIdx.x] = 0.0f;
        g_pmax[threadIdx.x] = -INFINITY;
    }
}

// ---------------- CSR build ---------------------------------------------------
__global__ void k_scan1() {
    __shared__ int sh[256];
    int t = threadIdx.x;
    int i = blockIdx.x * 256 + t;
    int v = (i < NN) ? g_ideg[i] : 0;
    sh[t] = v;
    __syncthreads();
    #pragma unroll
    for (int off = 1; off < 256; off <<= 1) {
        int add = (t >= off) ? sh[t - off] : 0;
        __syncthreads();
        sh[t] += add;
        __syncthreads();
    }
    if (i < NN) g_rowstart[i] = sh[t] - v;
    if (t == 255) g_blksum[blockIdx.x] = sh[255];
}

__global__ void k_scan2(int nblk) {
    __shared__ int sh[512];
    int t = threadIdx.x;
    int v = (t < nblk) ? g_blksum[t] : 0;
    sh[t] = v;
    __syncthreads();
    #pragma unroll
    for (int off = 1; off < 512; off <<= 1) {
        int add = (t >= off) ? sh[t - off] : 0;
        __syncthreads();
        sh[t] += add;
        __syncthreads();
    }
    if (t < nblk) g_blksum[t] = sh[t] - v;
}

__global__ void k_scan3() {
    int i = blockIdx.x * blockDim.x + threadIdx.x;
    if (i < NN) {
        g_rowstart[i] += g_blksum[i >> 8];
        g_cursor[i] = 0;
    }
    if (i == 0) g_rowstart[NN] = EE;
}

__global__ void k_csr_fill(const int* __restrict__ src, const int* __restrict__ dst) {
    int e = blockIdx.x * blockDim.x + threadIdx.x;
    if (e < EE) {
        int d = dst[e];
        int pos = atomicAdd(&g_cursor[d], 1);
        g_csr_src[g_rowstart[d] + pos] = src[e];
    }
}

// ---------------- tensor-core GEMM (bf16x3, m16n8k16) ------------------------
// C[N,256] = (A[N,K] * norm[row]) @ W[K,256]
// BM=128, BN=128, BK=16, 256 threads = 8 warps, warp tile 32(m) x 64(n).
// smem: A [m][k2] (k-pairs packed bf16x2), stride 12; B [k2][n], stride 136.
template <int K>
__global__ void __launch_bounds__(256, 2)
k_gemm_tc(const float* __restrict__ A, const float* __restrict__ W,
          const float* __restrict__ norm, float* __restrict__ C) {
    __shared__ uint32_t Ah[128][12];
    __shared__ uint32_t Al[128][12];
    __shared__ uint32_t Bh[8][136];
    __shared__ uint32_t Bl[8][136];

    const int tid  = threadIdx.x;
    const int lane = tid & 31;
    const int wid  = tid >> 5;
    const int wm   = wid >> 1;       // 0..3
    const int wn   = wid & 1;        // 0..1
    const int m0   = blockIdx.y * 128;
    const int n0   = blockIdx.x * 128;

    // A loader: thread covers rows a_r0, a_r0+64, k = a_c..a_c+3 (one float4)
    const int a_r0 = tid >> 2;             // 0..63
    const int a_r1 = a_r0 + 64;
    const int a_c  = (tid & 3) << 2;       // 0,4,8,12
    const int a_k2 = (tid & 3) << 1;       // 0,2,4,6 (packed col)
    // B loader: thread covers k rows kb_e,kb_e+1 and n = b_c..b_c+3
    const int kb_e = (tid >> 5) << 1;      // 0,2,..,14
    const int b_k2 = tid >> 5;             // 0..7
    const int b_c  = (tid & 31) << 2;      // 0..124

    const float nrm0 = (m0 + a_r0 < NN) ? norm[m0 + a_r0] : 0.f;
    const float nrm1 = (m0 + a_r1 < NN) ? norm[m0 + a_r1] : 0.f;

    float acc[2][8][4];
    #pragma unroll
    for (int mt = 0; mt < 2; mt++)
        #pragma unroll
        for (int nt = 0; nt < 8; nt++)
            #pragma unroll
            for (int i = 0; i < 4; i++) acc[mt][nt][i] = 0.f;

    float4 pa0, pa1, pb0, pb1;

    #define LOAD_TILE(kt)                                                         \
        {                                                                         \
            int kbase = (kt) * 16;                                                \
            pa0 = (m0 + a_r0 < NN)                                                \
                ? *(const float4*)(A + (size_t)(m0 + a_r0) * K + kbase + a_c)     \
                : make_float4(0.f, 0.f, 0.f, 0.f);                                \
            pa1 = (m0 + a_r1 < NN)                                                \
                ? *(const float4*)(A + (size_t)(m0 + a_r1) * K + kbase + a_c)     \
                : make_float4(0.f, 0.f, 0.f, 0.f);                                \
            pb0 = *(const float4*)(W + (size_t)(kbase + kb_e) * HH + n0 + b_c);   \
            pb1 = *(const float4*)(W + (size_t)(kbase + kb_e + 1) * HH + n0 + b_c); \
        }

    #define STORE_TILE()                                                          \
        {                                                                         \
            uint32_t h01, l01, h23, l23;                                          \
            bf16x3_pack(pa0.x * nrm0, pa0.y * nrm0, h01, l01);                    \
            bf16x3_pack(pa0.z * nrm0, pa0.w * nrm0, h23, l23);                    \
            *(uint2*)&Ah[a_r0][a_k2] = make_uint2(h01, h23);                      \
            *(uint2*)&Al[a_r0][a_k2] = make_uint2(l01, l23);                      \
            bf16x3_pack(pa1.x * nrm1, pa1.y * nrm1, h01, l01);                    \
            bf16x3_pack(pa1.z * nrm1, pa1.w * nrm1, h23, l23);                    \
            *(uint2*)&Ah[a_r1][a_k2] = make_uint2(h01, h23);                      \
            *(uint2*)&Al[a_r1][a_k2] = make_uint2(l01, l23);                      \
            uint32_t bh0, bl0, bh1, bl1, bh2, bl2, bh3, bl3;                      \
            bf16x3_pack(pb0.x, pb1.x, bh0, bl0);                                  \
            bf16x3_pack(pb0.y, pb1.y, bh1, bl1);                                  \
            bf16x3_pack(pb0.z, pb1.z, bh2, bl2);                                  \
            bf16x3_pack(pb0.w, pb1.w, bh3, bl3);                                  \
            *(uint4*)&Bh[b_k2][b_c] = make_uint4(bh0, bh1, bh2, bh3);             \
            *(uint4*)&Bl[b_k2][b_c] = make_uint4(bl0, bl1, bl2, bl3);             \
        }

    constexpr int KT = K / 16;

    LOAD_TILE(0);
    STORE_TILE();
    __syncthreads();

    const int g   = lane >> 2;     // 0..7
    const int tig = lane & 3;      // 0..3

    for (int kt = 0; kt < KT; kt++) {
        if (kt + 1 < KT) LOAD_TILE(kt + 1);

        // ---- fragment loads (conflict-free by construction) ----
        uint32_t ah[2][4], al[2][4];
        #pragma unroll
        for (int mt = 0; mt < 2; mt++) {
            int ra = wm * 32 + mt * 16 + g;
            ah[mt][0] = Ah[ra][tig];
            ah[mt][1] = Ah[ra + 8][tig];
            ah[mt][2] = Ah[ra][tig + 4];
            ah[mt][3] = Ah[ra + 8][tig + 4];
        }
        uint32_t bh[8][2];
        #pragma unroll
        for (int nt = 0; nt < 8; nt++) {
            int nb = wn * 64 + nt * 8 + g;
            bh[nt][0] = Bh[tig][nb];
            bh[nt][1] = Bh[tig + 4][nb];
        }
        // pass 1: Ah * Bh
        #pragma unroll
        for (int mt = 0; mt < 2; mt++)
            #pragma unroll
            for (int nt = 0; nt < 8; nt++)
                mma_bf16(acc[mt][nt], ah[mt], bh[nt]);

        // pass 2: Ah * Bl
        uint32_t bl[8][2];
        #pragma unroll
        for (int nt = 0; nt < 8; nt++) {
            int nb = wn * 64 + nt * 8 + g;
            bl[nt][0] = Bl[tig][nb];
            bl[nt][1] = Bl[tig + 4][nb];
        }
        #pragma unroll
        for (int mt = 0; mt < 2; mt++)
            #pragma unroll
            for (int nt = 0; nt < 8; nt++)
                mma_bf16(acc[mt][nt], ah[mt], bl[nt]);

        // pass 3: Al * Bh
        #pragma unroll
        for (int mt = 0; mt < 2; mt++) {
            int ra = wm * 32 + mt * 16 + g;
            al[mt][0] = Al[ra][tig];
            al[mt][1] = Al[ra + 8][tig];
            al[mt][2] = Al[ra][tig + 4];
            al[mt][3] = Al[ra + 8][tig + 4];
        }
        #pragma unroll
        for (int mt = 0; mt < 2; mt++)
            #pragma unroll
            for (int nt = 0; nt < 8; nt++)
                mma_bf16(acc[mt][nt], al[mt], bh[nt]);

        __syncthreads();
        if (kt + 1 < KT) {
            STORE_TILE();
            __syncthreads();
        }
    }

    // epilogue (same C layout as m16n8k8)
    #pragma unroll
    for (int mt = 0; mt < 2; mt++) {
        #pragma unroll
        for (int nt = 0; nt < 8; nt++) {
            int row = m0 + wm * 32 + mt * 16 + g;
            int col = n0 + wn * 64 + nt * 8 + tig * 2;
            if (row < NN)
                *(float2*)(C + (size_t)row * HH + col) =
                    make_float2(acc[mt][nt][0], acc[mt][nt][1]);
            if (row + 8 < NN)
                *(float2*)(C + (size_t)(row + 8) * HH + col) =
                    make_float2(acc[mt][nt][2], acc[mt][nt][3]);
        }
    }
    #undef LOAD_TILE
    #undef STORE_TILE
}

// ---------------- CSR gather: smem-staged indices, 4-edge unrolled ----------
template <bool POOL>
__global__ void __launch_bounds__(256)
k_gather(const float4* __restrict__ X, float4* __restrict__ O,
         const float* __restrict__ ndst, const float* __restrict__ bias) {
    __shared__ int   s_idx[8][128];
    __shared__ float s_sum[HH];
    __shared__ float s_max[HH];

    const int lane = threadIdx.x & 31;
    const int wip  = threadIdx.x >> 5;
    const int n    = (blockIdx.x * blockDim.x + threadIdx.x) >> 5;

    if (POOL) {
        s_sum[threadIdx.x] = 0.0f;
        s_max[threadIdx.x] = -INFINITY;
        __syncthreads();
    }

    float4 o0, o1;
    const bool valid = (n < NN);
    if (valid) {
        const int beg = g_rowstart[n];
        const int cnt = g_rowstart[n + 1] - beg;
        float4 a0 = make_float4(0.f, 0.f, 0.f, 0.f);
        float4 a1 = make_float4(0.f, 0.f, 0.f, 0.f);

        for (int base = 0; base < cnt; base += 128) {
            const int chunk = min(128, cnt - base);
            for (int j = lane; j < chunk; j += 32)
                s_idx[wip][j] = __ldg(&g_csr_src[beg + base + j]);
            __syncwarp();

            int j = 0;
            for (; j + 4 <= chunk; j += 4) {
                int s0 = s_idx[wip][j + 0];
                int s1 = s_idx[wip][j + 1];
                int s2 = s_idx[wip][j + 2];
                int s3 = s_idx[wip][j + 3];
                const float4* x0 = X + (size_t)s0 * (HH / 4);
                const float4* x1 = X + (size_t)s1 * (HH / 4);
                const float4* x2 = X + (size_t)s2 * (HH / 4);
                const float4* x3 = X + (size_t)s3 * (HH / 4);
                float4 v00 = x0[lane];      float4 v01 = x0[lane + 32];
                float4 v10 = x1[lane];      float4 v11 = x1[lane + 32];
                float4 v20 = x2[lane];      float4 v21 = x2[lane + 32];
                float4 v30 = x3[lane];      float4 v31 = x3[lane + 32];
                a0 = f4add(a0, f4add(f4add(v00, v10), f4add(v20, v30)));
                a1 = f4add(a1, f4add(f4add(v01, v11), f4add(v21, v31)));
            }
            for (; j < chunk; j++) {
                int s = s_idx[wip][j];
                const float4* xs = X + (size_t)s * (HH / 4);
                a0 = f4add(a0, xs[lane]);
                a1 = f4add(a1, xs[lane + 32]);
            }
            __syncwarp();
        }

        const float nd = ndst[n];
        float4 bb0 = ((const float4*)bias)[lane];
        float4 bb1 = ((const float4*)bias)[lane + 32];
        o0.x = leaky(fmaf(a0.x, nd, bb0.x));
        o0.y = leaky(fmaf(a0.y, nd, bb0.y));
        o0.z = leaky(fmaf(a0.z, nd, bb0.z));
        o0.w = leaky(fmaf(a0.w, nd, bb0.w));
        o1.x = leaky(fmaf(a1.x, nd, bb1.x));
        o1.y = leaky(fmaf(a1.y, nd, bb1.y));
        o1.z = leaky(fmaf(a1.z, nd, bb1.z));
        o1.w = leaky(fmaf(a1.w, nd, bb1.w));

        if (POOL) {
            __stcs(&O[(size_t)n * (HH / 4) + lane], o0);
            __stcs(&O[(size_t)n * (HH / 4) + lane + 32], o1);
        } else {
            O[(size_t)n * (HH / 4) + lane]      = o0;
            O[(size_t)n * (HH / 4) + lane + 32] = o1;
        }
    }

    if (POOL) {
        if (valid) {
            const int c0 = lane * 4;
            const int c1 = 128 + lane * 4;
            atomicAdd(&s_sum[c0 + 0], o0.x); atomicAdd(&s_sum[c0 + 1], o0.y);
            atomicAdd(&s_sum[c0 + 2], o0.z); atomicAdd(&s_sum[c0 + 3], o0.w);
            atomicAdd(&s_sum[c1 + 0], o1.x); atomicAdd(&s_sum[c1 + 1], o1.y);
            atomicAdd(&s_sum[c1 + 2], o1.z); atomicAdd(&s_sum[c1 + 3], o1.w);
            atomicMaxFloat(&s_max[c0 + 0], o0.x); atomicMaxFloat(&s_max[c0 + 1], o0.y);
            atomicMaxFloat(&s_max[c0 + 2], o0.z); atomicMaxFloat(&s_max[c0 + 3], o0.w);
            atomicMaxFloat(&s_max[c1 + 0], o1.x); atomicMaxFloat(&s_max[c1 + 1], o1.y);
            atomicMaxFloat(&s_max[c1 + 2], o1.z); atomicMaxFloat(&s_max[c1 + 3], o1.w);
        }
        __syncthreads();
        atomicAdd(&g_psum[threadIdx.x], s_sum[threadIdx.x]);
        atomicMaxFloat(&g_pmax[threadIdx.x], s_max[threadIdx.x]);
    }
}

// ---------------- generator head ---------------------------------------------
__global__ void k_final(const float* __restrict__ B, const int* __restrict__ node_index,
                        const float* __restrict__ b2,
                        const float* __restrict__ Wg, const float* __restrict__ bg,
                        const float* __restrict__ eps, float* __restrict__ out) {
    __shared__ float pooled[768];
    __shared__ float red[256];
    int t  = threadIdx.x;
    int ni = *node_index;

    pooled[t]       = g_psum[t];
    pooled[256 + t] = g_pmax[t];
    pooled[512 + t] = B[(size_t)ni * HH + t];
    __syncthreads();

    float fdv[4];
    #pragma unroll
    for (int o = 0; o < 4; o++) {
        int k = t + o * 256;
        float acc = bg[k];
        for (int i = 0; i < 768; i++)
            acc = fmaf(pooled[i], Wg[(size_t)i * 1024 + k], acc);
        fdv[o] = acc;
    }
    float mu1 = fdv[0],        mu2 = fdv[1];
    float sg1 = fabsf(fdv[2]), sg2 = fabsf(fdv[3]);
    float e1 = eps[t], e2 = eps[t + 256];
    float fn1 = fmaf(sg1, e1, mu1);
    float fn2 = fmaf(sg2, e2, mu2);

    out[t]              = fn1;  out[t + 256]        = fn2;
    out[512 + t]        = mu1;  out[512 + t + 256]  = mu2;
    out[1024 + t]       = sg1;  out[1024 + t + 256] = sg2;

    const float HALF_LOG_2PI = 0.9189385332046727f;
    float r1 = (fn1 - mu1) / sg1;
    float r2 = (fn2 - mu2) / sg2;
    float lp = (-0.5f * r1 * r1 - logf(sg1) - HALF_LOG_2PI)
             + (-0.5f * r2 * r2 - logf(sg2) - HALF_LOG_2PI);
    red[t] = lp;
    __syncthreads();
    for (int off = 128; off > 0; off >>= 1) {
        if (t < off) red[t] += red[t + off];
        __syncthreads();
    }
    if (t == 0) out[1536] = red[0] / 512.0f;
}

// ---------------- launcher ----------------------------------------------------
extern "C" void kernel_launch(void* const* d_in, const int* in_sizes, int n_in,
                              void* d_out, int out_size) {
    const float* feat = (const float*)d_in[0];
    const int*   src  = (const int*)d_in[1];
    const int*   dst  = (const int*)d_in[2];
    const int*   nidx = (const int*)d_in[3];
    const float* W1   = (const float*)d_in[4];
    const float* b1   = (const float*)d_in[5];
    const float* W2   = (const float*)d_in[6];
    const float* b2   = (const float*)d_in[7];
    const float* Wg   = (const float*)d_in[8];
    const float* bg   = (const float*)d_in[9];
    const float* eps  = (const float*)d_in[10];
    float* out = (float*)d_out;

    void *p0, *p1, *p2, *pns, *pnd;
    cudaGetSymbolAddress(&p0, g_B0);
    cudaGetSymbolAddress(&p1, g_B1);
    cudaGetSymbolAddress(&p2, g_B2);
    cudaGetSymbolAddress(&pns, g_nsrc);
    cudaGetSymbolAddress(&pnd, g_ndst);
    float* B0 = (float*)p0;
    float* B1 = (float*)p1;
    float* B2 = (float*)p2;
    float* nsrc = (float*)pns;
    float* ndst = (float*)pnd;

    const int DEG_BLKS  = (EE + 255) / 256;
    const int N_BLKS    = (NN + 255) / 256;      // 391
    const dim3 GEMM_GRID(2, (NN + 127) / 128);   // 782 m-tiles x 2 n-tiles
    const int GATH_BLKS = (NN + 7) / 8;          // one warp per node

    // launch order chosen so stream index 3 (the ncu-profiled slot) is gemm1
    k_prep<<<N_BLKS, 256>>>();                                   // 0
    k_degree<<<DEG_BLKS, 256>>>(src, dst);                       // 1
    k_norm<<<N_BLKS, 256>>>();                                   // 2
    k_gemm_tc<FF><<<GEMM_GRID, 256>>>(feat, W1, nsrc, B0);       // 3  <- profiled
    k_scan1<<<N_BLKS, 256>>>();                                  // 4
    k_scan2<<<1, 512>>>(N_BLKS);                                 // 5
    k_scan3<<<N_BLKS, 256>>>();                                  // 6
    k_csr_fill<<<DEG_BLKS, 256>>>(src, dst);                     // 7
    k_gather<false><<<GATH_BLKS, 256>>>((const float4*)B0, (float4*)B1, ndst, b1); // 8
    k_gemm_tc<HH><<<GEMM_GRID, 256>>>(B1, W2, nsrc, B2);         // 9
    k_gather<true><<<GATH_BLKS, 256>>>((const float4*)B2, (float4*)B0, ndst, b2);  // 10
    k_final<<<1, 256>>>(B0, nidx, b2, Wg, bg, eps, out);         // 11
}

// round 12
// speedup vs baseline: 1.4800x; 1.0394x over previous
#include <cuda_runtime.h>
#include <math.h>
#include <stdint.h>

#define NN 100000
#define EE 1600000
#define FF 512
#define HH 256

// ---------------- scratch (static device globals; no allocation) ------------
__device__ float g_B0[(size_t)NN * HH];
__device__ float g_B1[(size_t)NN * HH];
__device__ float g_B2[(size_t)NN * HH];
__device__ int   g_odeg[NN];
__device__ int   g_ideg[NN];
__device__ float g_nsrc[NN];
__device__ float g_ndst[NN];
__device__ float g_psum[HH];
__device__ float g_pmax[HH];
// CSR (in-edges grouped by dst)
__device__ int   g_rowstart[NN + 1];
__device__ int   g_cursor[NN];
__device__ int   g_csr_src[EE];
__device__ int   g_blksum[512];

// ---------------- helpers ---------------------------------------------------
__device__ __forceinline__ void atomicMaxFloat(float* addr, float v) {
    if (v >= 0.0f) atomicMax((int*)addr, __float_as_int(v));
    else           atomicMin((unsigned int*)addr, __float_as_uint(v));
}

__device__ __forceinline__ float leaky(float x) {
    return x > 0.0f ? x : 0.01f * x;
}

struct f8 { float a0, a1, a2, a3, a4, a5, a6, a7; };

// 256-bit global load (sm_100+): one LDG.E.256 per call
__device__ __forceinline__ f8 ldg256(const float* p) {
    f8 v;
    asm volatile("ld.global.nc.v8.f32 {%0,%1,%2,%3,%4,%5,%6,%7}, [%8];"
                 : "=f"(v.a0), "=f"(v.a1), "=f"(v.a2), "=f"(v.a3),
                   "=f"(v.a4), "=f"(v.a5), "=f"(v.a6), "=f"(v.a7)
                 : "l"(p));
    return v;
}
__device__ __forceinline__ void f8acc(f8& a, const f8& b) {
    a.a0 += b.a0; a.a1 += b.a1; a.a2 += b.a2; a.a3 += b.a3;
    a.a4 += b.a4; a.a5 += b.a5; a.a6 += b.a6; a.a7 += b.a7;
}

__device__ __forceinline__ uint16_t f2bf(float x) {
    uint16_t r;
    asm("cvt.rn.bf16.f32 %0, %1;" : "=h"(r) : "f"(x));
    return r;
}
__device__ __forceinline__ float bf2f(uint16_t b) {
    return __uint_as_float(((uint32_t)b) << 16);
}
__device__ __forceinline__ void bf16x3_pack(float x, float y, uint32_t& hi, uint32_t& lo) {
    uint16_t hx = f2bf(x);
    uint16_t hy = f2bf(y);
    uint16_t lx = f2bf(x - bf2f(hx));
    uint16_t ly = f2bf(y - bf2f(hy));
    hi = (uint32_t)hx | ((uint32_t)hy << 16);
    lo = (uint32_t)lx | ((uint32_t)ly << 16);
}

__device__ __forceinline__ void mma_bf16(float* d, const uint32_t* a, const uint32_t* b) {
    asm volatile(
        "mma.sync.aligned.m16n8k16.row.col.f32.bf16.bf16.f32 "
        "{%0,%1,%2,%3}, {%4,%5,%6,%7}, {%8,%9}, {%0,%1,%2,%3};\n"
        : "+f"(d[0]), "+f"(d[1]), "+f"(d[2]), "+f"(d[3])
        : "r"(a[0]), "r"(a[1]), "r"(a[2]), "r"(a[3]), "r"(b[0]), "r"(b[1]));
}

__device__ __forceinline__ void ldsm4(uint32_t* r, const uint32_t* p) {
    uint32_t a = (uint32_t)__cvta_generic_to_shared(p);
    asm volatile("ldmatrix.sync.aligned.m8n8.x4.shared.b16 {%0,%1,%2,%3}, [%4];"
                 : "=r"(r[0]), "=r"(r[1]), "=r"(r[2]), "=r"(r[3]) : "r"(a));
}

// ---------------- small kernels ---------------------------------------------
__global__ void k_prep() {
    int i = blockIdx.x * blockDim.x + threadIdx.x;
    if (i < NN) {
        g_odeg[i] = 0;
        g_ideg[i] = 0;
    }
}

__global__ void k_degree(const int* __restrict__ src, const int* __restrict__ dst) {
    int e = blockIdx.x * blockDim.x + threadIdx.x;
    if (e < EE) {
        atomicAdd(&g_odeg[src[e]], 1);
        atomicAdd(&g_ideg[dst[e]], 1);
    }
}

__global__ void k_norm() {
    int i = blockIdx.x * blockDim.x + threadIdx.x;
    if (i < NN) {
        g_nsrc[i] = rsqrtf(fmaxf((float)g_odeg[i], 1.0f));
        g_ndst[i] = rsqrtf(fmaxf((float)g_ideg[i], 1.0f));
    }
    if (blockIdx.x == 0 && threadIdx.x < HH) {
        g_psum[threadIdx.x] = 0.0f;
        g_pmax[threadIdx.x] = -INFINITY;
    }
}

// ---------------- CSR build ---------------------------------------------------
__global__ void k_scan1() {
    __shared__ int sh[256];
    int t = threadIdx.x;
    int i = blockIdx.x * 256 + t;
    int v = (i < NN) ? g_ideg[i] : 0;
    sh[t] = v;
    __syncthreads();
    #pragma unroll
    for (int off = 1; off < 256; off <<= 1) {
        int add = (t >= off) ? sh[t - off] : 0;
        __syncthreads();
        sh[t] += add;
        __syncthreads();
    }
    if (i < NN) g_rowstart[i] = sh[t] - v;
    if (t == 255) g_blksum[blockIdx.x] = sh[255];
}

__global__ void k_scan2(int nblk) {
    __shared__ int sh[512];
    int t = threadIdx.x;
    int v = (t < nblk) ? g_blksum[t] : 0;
    sh[t] = v;
    __syncthreads();
    #pragma unroll
    for (int off = 1; off < 512; off <<= 1) {
        int add = (t >= off) ? sh[t - off] : 0;
        __syncthreads();
        sh[t] += add;
        __syncthreads();
    }
    if (t < nblk) g_blksum[t] = sh[t] - v;
}

__global__ void k_scan3() {
    int i = blockIdx.x * blockDim.x + threadIdx.x;
    if (i < NN) {
        g_rowstart[i] += g_blksum[i >> 8];
        g_cursor[i] = 0;
    }
    if (i == 0) g_rowstart[NN] = EE;
}

__global__ void k_csr_fill(const int* __restrict__ src, const int* __restrict__ dst) {
    int e = blockIdx.x * blockDim.x + threadIdx.x;
    if (e < EE) {
        int d = dst[e];
        int pos = atomicAdd(&g_cursor[d], 1);
        g_csr_src[g_rowstart[d] + pos] = src[e];
    }
}

// ---------------- tensor-core GEMM (bf16x3, m16n8k16, ldmatrix A) -------------
// C[N,256] = (A[N,K] * norm[row]) @ W[K,256]
// BM=128, BN=128, BK=16, 8 warps, warp tile 64(m) x 32(n).
template <int K>
__global__ void __launch_bounds__(256, 2)
k_gemm_tc(const float* __restrict__ A, const float* __restrict__ W,
          const float* __restrict__ norm, float* __restrict__ C) {
    __shared__ __align__(16) uint32_t Ah[128][12];
    __shared__ __align__(16) uint32_t Al[128][12];
    __shared__ __align__(16) uint32_t Bh[8][136];
    __shared__ __align__(16) uint32_t Bl[8][136];

    const int tid  = threadIdx.x;
    const int lane = tid & 31;
    const int wid  = tid >> 5;
    const int wm   = wid & 1;        // m block of 64
    const int wn   = wid >> 1;       // n block of 32
    const int m0   = blockIdx.y * 128;
    const int n0   = blockIdx.x * 128;

    const int a_r0 = tid >> 2;
    const int a_r1 = a_r0 + 64;
    const int a_c  = (tid & 3) << 2;
    const int a_k2 = (tid & 3) << 1;
    const int kb_e = (tid >> 5) << 1;
    const int b_k2 = tid >> 5;
    const int b_c  = (tid & 31) << 2;

    const float nrm0 = (m0 + a_r0 < NN) ? norm[m0 + a_r0] : 0.f;
    const float nrm1 = (m0 + a_r1 < NN) ? norm[m0 + a_r1] : 0.f;

    const int lm_r = (lane & 7) + ((lane >> 3) & 1) * 8;   // 0..15
    const int lm_c = (lane >> 4) * 4;                      // 0 or 4
    const int g    = lane >> 2;
    const int tig  = lane & 3;

    float acc[4][4][4];
    #pragma unroll
    for (int mt = 0; mt < 4; mt++)
        #pragma unroll
        for (int nt = 0; nt < 4; nt++)
            #pragma unroll
            for (int i = 0; i < 4; i++) acc[mt][nt][i] = 0.f;

    float4 pa0, pa1, pb0, pb1;

    #define LOAD_TILE(kt)                                                         \
        {                                                                         \
            int kbase = (kt) * 16;                                                \
            pa0 = (m0 + a_r0 < NN)                                                \
                ? *(const float4*)(A + (size_t)(m0 + a_r0) * K + kbase + a_c)     \
                : make_float4(0.f, 0.f, 0.f, 0.f);                                \
            pa1 = (m0 + a_r1 < NN)                                                \
                ? *(const float4*)(A + (size_t)(m0 + a_r1) * K + kbase + a_c)     \
                : make_float4(0.f, 0.f, 0.f, 0.f);                                \
            pb0 = *(const float4*)(W + (size_t)(kbase + kb_e) * HH + n0 + b_c);   \
            pb1 = *(const float4*)(W + (size_t)(kbase + kb_e + 1) * HH + n0 + b_c); \
        }

    #define STORE_TILE()                                                          \
        {                                                                         \
            uint32_t h01, l01, h23, l23;                                          \
            bf16x3_pack(pa0.x * nrm0, pa0.y * nrm0, h01, l01);                    \
            bf16x3_pack(pa0.z * nrm0, pa0.w * nrm0, h23, l23);                    \
            *(uint2*)&Ah[a_r0][a_k2] = make_uint2(h01, h23);                      \
            *(uint2*)&Al[a_r0][a_k2] = make_uint2(l01, l23);                      \
            bf16x3_pack(pa1.x * nrm1, pa1.y * nrm1, h01, l01);                    \
            bf16x3_pack(pa1.z * nrm1, pa1.w * nrm1, h23, l23);                    \
            *(uint2*)&Ah[a_r1][a_k2] = make_uint2(h01, h23);                      \
            *(uint2*)&Al[a_r1][a_k2] = make_uint2(l01, l23);                      \
            uint32_t bh0, bl0, bh1, bl1, bh2, bl2, bh3, bl3;                      \
            bf16x3_pack(pb0.x, pb1.x, bh0, bl0);                                  \
            bf16x3_pack(pb0.y, pb1.y, bh1, bl1);                                  \
            bf16x3_pack(pb0.z, pb1.z, bh2, bl2);                                  \
            bf16x3_pack(pb0.w, pb1.w, bh3, bl3);                                  \
            *(uint4*)&Bh[b_k2][b_c] = make_uint4(bh0, bh1, bh2, bh3);             \
            *(uint4*)&Bl[b_k2][b_c] = make_uint4(bl0, bl1, bl2, bl3);             \
        }

    constexpr int KT = K / 16;

    LOAD_TILE(0);
    STORE_TILE();
    __syncthreads();

    for (int kt = 0; kt < KT; kt++) {
        if (kt + 1 < KT) LOAD_TILE(kt + 1);

        uint32_t ah[4][4];
        #pragma unroll
        for (int mt = 0; mt < 4; mt++)
            ldsm4(ah[mt], &Ah[wm * 64 + mt * 16 + lm_r][lm_c]);

        uint32_t bh[4][2];
        #pragma unroll
        for (int nt = 0; nt < 4; nt++) {
            int nb = wn * 32 + nt * 8 + g;
            bh[nt][0] = Bh[tig][nb];
            bh[nt][1] = Bh[tig + 4][nb];
        }
        #pragma unroll
        for (int mt = 0; mt < 4; mt++)
            #pragma unroll
            for (int nt = 0; nt < 4; nt++)
                mma_bf16(acc[mt][nt], ah[mt], bh[nt]);

        uint32_t bl[4][2];
        #pragma unroll
        for (int nt = 0; nt < 4; nt++) {
            int nb = wn * 32 + nt * 8 + g;
            bl[nt][0] = Bl[tig][nb];
            bl[nt][1] = Bl[tig + 4][nb];
        }
        #pragma unroll
        for (int mt = 0; mt < 4; mt++)
            #pragma unroll
            for (int nt = 0; nt < 4; nt++)
                mma_bf16(acc[mt][nt], ah[mt], bl[nt]);

        uint32_t al[4][4];
        #pragma unroll
        for (int mt = 0; mt < 4; mt++)
            ldsm4(al[mt], &Al[wm * 64 + mt * 16 + lm_r][lm_c]);
        #pragma unroll
        for (int mt = 0; mt < 4; mt++)
            #pragma unroll
            for (int nt = 0; nt < 4; nt++)
                mma_bf16(acc[mt][nt], al[mt], bh[nt]);

        __syncthreads();
        if (kt + 1 < KT) {
            STORE_TILE();
            __syncthreads();
        }
    }

    #pragma unroll
    for (int mt = 0; mt < 4; mt++) {
        #pragma unroll
        for (int nt = 0; nt < 4; nt++) {
            int row = m0 + wm * 64 + mt * 16 + g;
            int col = n0 + wn * 32 + nt * 8 + tig * 2;
            if (row < NN)
                *(float2*)(C + (size_t)row * HH + col) =
                    make_float2(acc[mt][nt][0], acc[mt][nt][1]);
            if (row + 8 < NN)
                *(float2*)(C + (size_t)(row + 8) * HH + col) =
                    make_float2(acc[mt][nt][2], acc[mt][nt][3]);
        }
    }
    #undef LOAD_TILE
    #undef STORE_TILE
}

// ---------------- CSR gather, column-split half pass, 256-bit loads ----------
// Processes 128 of 256 feature columns (floats [off*4, off*4+128)).
// One warp per node; half-warps each handle one edge per round (2 edges/round),
// each lane does ONE LDG.256 (32B) -> 16 lanes cover the 128-float half row.
template <bool POOL>
__global__ void __launch_bounds__(256)
k_gather_half(const float* __restrict__ X, float* __restrict__ O,
              const float* __restrict__ ndst, const float* __restrict__ bias,
              int off) {
    __shared__ int   s_idx[8][128];
    __shared__ float s_sum[128];
    __shared__ float s_max[128];

    const int lane = threadIdx.x & 31;
    const int half = lane >> 4;               // 0 or 1 (edge selector)
    const int hl   = lane & 15;               // lane within half-warp
    const int wip  = threadIdx.x >> 5;
    const int n    = (blockIdx.x * blockDim.x + threadIdx.x) >> 5;

    if (POOL) {
        if (threadIdx.x < 128) {
            s_sum[threadIdx.x] = 0.0f;
            s_max[threadIdx.x] = -INFINITY;
        }
        __syncthreads();
    }

    // this lane's 8-float slice within the 128-float half row
    const int fcol = off * 4 + hl * 8;

    f8 a = {0.f, 0.f, 0.f, 0.f, 0.f, 0.f, 0.f, 0.f};

    const bool valid = (n < NN);
    if (valid) {
        const int beg = g_rowstart[n];
        const int cnt = g_rowstart[n + 1] - beg;

        for (int base = 0; base < cnt; base += 128) {
            const int chunk = min(128, cnt - base);
            for (int j = lane; j < chunk; j += 32)
                s_idx[wip][j] = __ldg(&g_csr_src[beg + base + j]);
            __syncwarp();

            int j = 0;
            // 8 edges per round: each half-warp covers 4 of them -> 4 LDG.256/lane
            for (; j + 8 <= chunk; j += 8) {
                int e0 = s_idx[wip][j + half * 4 + 0];
                int e1 = s_idx[wip][j + half * 4 + 1];
                int e2 = s_idx[wip][j + half * 4 + 2];
                int e3 = s_idx[wip][j + half * 4 + 3];
                f8 v0 = ldg256(X + (size_t)e0 * HH + fcol);
                f8 v1 = ldg256(X + (size_t)e1 * HH + fcol);
                f8 v2 = ldg256(X + (size_t)e2 * HH + fcol);
                f8 v3 = ldg256(X + (size_t)e3 * HH + fcol);
                f8acc(a, v0); f8acc(a, v1); f8acc(a, v2); f8acc(a, v3);
            }
            // 2 edges per round
            for (; j + 2 <= chunk; j += 2) {
                int e0 = s_idx[wip][j + half];
                f8 v0 = ldg256(X + (size_t)e0 * HH + fcol);
                f8acc(a, v0);
            }
            // odd tail edge: only half 0 accumulates
            if (j < chunk && half == 0) {
                int e0 = s_idx[wip][j];
                f8 v0 = ldg256(X + (size_t)e0 * HH + fcol);
                f8acc(a, v0);
            }
            __syncwarp();
        }
    }

    // combine the two half-warp partial sums: lane L and L+16 hold the same
    // column slice for different edge subsets.
    #pragma unroll
    for (int i = 0; i < 8; i++) {
        float* pv = &a.a0 + i;
        float other = __shfl_xor_sync(0xffffffffu, *pv, 16);
        *pv += other;
    }

    float o[8];
    if (valid) {
        const float nd = ndst[n];
        #pragma unroll
        for (int i = 0; i < 8; i++) {
            float bb = __ldg(&bias[fcol + i]);
            o[i] = leaky(fmaf((&a.a0)[i], nd, bb));
        }
        // both halves now hold identical values; half 0 stores
        if (half == 0) {
            float4 o0 = make_float4(o[0], o[1], o[2], o[3]);
            float4 o1 = make_float4(o[4], o[5], o[6], o[7]);
            __stcs((float4*)(O + (size_t)n * HH + fcol), o0);
            __stcs((float4*)(O + (size_t)n * HH + fcol + 4), o1);
        }
    }

    if (POOL) {
        if (valid && half == 0) {
            const int c = hl * 8;        // local column base 0..120
            #pragma unroll
            for (int i = 0; i < 8; i++) {
                atomicAdd(&s_sum[c + i], o[i]);
                atomicMaxFloat(&s_max[c + i], o[i]);
            }
        }
        __syncthreads();
        if (threadIdx.x < 128) {
            atomicAdd(&g_psum[off * 4 + threadIdx.x], s_sum[threadIdx.x]);
            atomicMaxFloat(&g_pmax[off * 4 + threadIdx.x], s_max[threadIdx.x]);
        }
    }
}

// ---------------- generator head ---------------------------------------------
__global__ void k_final(const float* __restrict__ B, const int* __restrict__ node_index,
                        const float* __restrict__ b2,
                        const float* __restrict__ Wg, const float* __restrict__ bg,
                        const float* __restrict__ eps, float* __restrict__ out) {
    __shared__ float pooled[768];
    __shared__ float red[256];
    int t  = threadIdx.x;
    int ni = *node_index;

    pooled[t]       = g_psum[t];
    pooled[256 + t] = g_pmax[t];
    pooled[512 + t] = B[(size_t)ni * HH + t];
    __syncthreads();

    float fdv[4];
    #pragma unroll
    for (int o = 0; o < 4; o++) {
        int k = t + o * 256;
        float acc = bg[k];
        for (int i = 0; i < 768; i++)
            acc = fmaf(pooled[i], Wg[(size_t)i * 1024 + k], acc);
        fdv[o] = acc;
    }
    float mu1 = fdv[0],        mu2 = fdv[1];
    float sg1 = fabsf(fdv[2]), sg2 = fabsf(fdv[3]);
    float e1 = eps[t], e2 = eps[t + 256];
    float fn1 = fmaf(sg1, e1, mu1);
    float fn2 = fmaf(sg2, e2, mu2);

    out[t]              = fn1;  out[t + 256]        = fn2;
    out[512 + t]        = mu1;  out[512 + t + 256]  = mu2;
    out[1024 + t]       = sg1;  out[1024 + t + 256] = sg2;

    const float HALF_LOG_2PI = 0.9189385332046727f;
    float r1 = (fn1 - mu1) / sg1;
    float r2 = (fn2 - mu2) / sg2;
    float lp = (-0.5f * r1 * r1 - logf(sg1) - HALF_LOG_2PI)
             + (-0.5f * r2 * r2 - logf(sg2) - HALF_LOG_2PI);
    red[t] = lp;
    __syncthreads();
    for (int off = 128; off > 0; off >>= 1) {
        if (t < off) red[t] += red[t + off];
        __syncthreads();
    }
    if (t == 0) out[1536] = red[0] / 512.0f;
}

// ---------------- launcher ----------------------------------------------------
extern "C" void kernel_launch(void* const* d_in, const int* in_sizes, int n_in,
                              void* d_out, int out_size) {
    const float* feat = (const float*)d_in[0];
    const int*   src  = (const int*)d_in[1];
    const int*   dst  = (const int*)d_in[2];
    const int*   nidx = (const int*)d_in[3];
    const float* W1   = (const float*)d_in[4];
    const float* b1   = (const float*)d_in[5];
    const float* W2   = (const float*)d_in[6];
    const float* b2   = (const float*)d_in[7];
    const float* Wg   = (const float*)d_in[8];
    const float* bg   = (const float*)d_in[9];
    const float* eps  = (const float*)d_in[10];
    float* out = (float*)d_out;

    void *p0, *p1, *p2, *pns, *pnd;
    cudaGetSymbolAddress(&p0, g_B0);
    cudaGetSymbolAddress(&p1, g_B1);
    cudaGetSymbolAddress(&p2, g_B2);
    cudaGetSymbolAddress(&pns, g_nsrc);
    cudaGetSymbolAddress(&pnd, g_ndst);
    float* B0 = (float*)p0;
    float* B1 = (float*)p1;
    float* B2 = (float*)p2;
    float* nsrc = (float*)pns;
    float* ndst = (float*)pnd;

    const int DEG_BLKS  = (EE + 255) / 256;
    const int N_BLKS    = (NN + 255) / 256;      // 391
    const dim3 GEMM_GRID(2, (NN + 127) / 128);   // 782 m-tiles x 2 n-tiles
    const int GATH_BLKS = (NN + 7) / 8;          // one warp per node

    // launch order: stream index 3 (the ncu-profiled slot) is gemm1
    k_prep<<<N_BLKS, 256>>>();                                   // 0
    k_degree<<<DEG_BLKS, 256>>>(src, dst);                       // 1
    k_norm<<<N_BLKS, 256>>>();                                   // 2
    k_gemm_tc<FF><<<GEMM_GRID, 256>>>(feat, W1, nsrc, B0);       // 3  <- profiled
    k_scan1<<<N_BLKS, 256>>>();                                  // 4
    k_scan2<<<1, 512>>>(N_BLKS);                                 // 5
    k_scan3<<<N_BLKS, 256>>>();                                  // 6
    k_csr_fill<<<DEG_BLKS, 256>>>(src, dst);                     // 7

    // layer 1 gather, two L2-resident half passes
    k_gather_half<false><<<GATH_BLKS, 256>>>(B0, B1, ndst, b1, 0);
    k_gather_half<false><<<GATH_BLKS, 256>>>(B0, B1, ndst, b1, 32);

    // layer 2
    k_gemm_tc<HH><<<GEMM_GRID, 256>>>(B1, W2, nsrc, B2);
    k_gather_half<true><<<GATH_BLKS, 256>>>(B2, B0, ndst, b2, 0);
    k_gather_half<true><<<GATH_BLKS, 256>>>(B2, B0, ndst, b2, 32);

    // head
    k_final<<<1, 256>>>(B0, nidx, b2, Wg, bg, eps, out);
}

// round 15
// speedup vs baseline: 1.4837x; 1.0025x over previous
#include <cuda_runtime.h>
#include <math.h>
#include <stdint.h>

#define NN 100000
#define EE 1600000
#define FF 512
#define HH 256

// ---------------- scratch (static device globals; no allocation) ------------
__device__ float g_B0[(size_t)NN * HH];
__device__ float g_B1[(size_t)NN * HH];
__device__ float g_B2[(size_t)NN * HH];
__device__ int   g_odeg[NN];
__device__ int   g_ideg[NN];
__device__ float g_nsrc[NN];
__device__ float g_ndst[NN];
__device__ float g_psum[HH];
__device__ float g_pmax[HH];
// CSR (in-edges grouped by dst)
__device__ int   g_rowstart[NN + 1];
__device__ int   g_cursor[NN];
__device__ int   g_csr_src[EE];
__device__ int   g_blksum[512];

// ---------------- helpers ---------------------------------------------------
__device__ __forceinline__ void atomicMaxFloat(float* addr, float v) {
    if (v >= 0.0f) atomicMax((int*)addr, __float_as_int(v));
    else           atomicMin((unsigned int*)addr, __float_as_uint(v));
}

__device__ __forceinline__ float leaky(float x) {
    return x > 0.0f ? x : 0.01f * x;
}

struct f8 { float a0, a1, a2, a3, a4, a5, a6, a7; };

// 256-bit global load (sm_100+): one LDG.E.256 per call
__device__ __forceinline__ f8 ldg256(const float* p) {
    f8 v;
    asm volatile("ld.global.nc.v8.f32 {%0,%1,%2,%3,%4,%5,%6,%7}, [%8];"
                 : "=f"(v.a0), "=f"(v.a1), "=f"(v.a2), "=f"(v.a3),
                   "=f"(v.a4), "=f"(v.a5), "=f"(v.a6), "=f"(v.a7)
                 : "l"(p));
    return v;
}
__device__ __forceinline__ void f8acc(f8& a, const f8& b) {
    a.a0 += b.a0; a.a1 += b.a1; a.a2 += b.a2; a.a3 += b.a3;
    a.a4 += b.a4; a.a5 += b.a5; a.a6 += b.a6; a.a7 += b.a7;
}

__device__ __forceinline__ uint16_t f2bf(float x) {
    uint16_t r;
    asm("cvt.rn.bf16.f32 %0, %1;" : "=h"(r) : "f"(x));
    return r;
}
__device__ __forceinline__ float bf2f(uint16_t b) {
    return __uint_as_float(((uint32_t)b) << 16);
}
__device__ __forceinline__ void bf16x3_pack(float x, float y, uint32_t& hi, uint32_t& lo) {
    uint16_t hx = f2bf(x);
    uint16_t hy = f2bf(y);
    uint16_t lx = f2bf(x - bf2f(hx));
    uint16_t ly = f2bf(y - bf2f(hy));
    hi = (uint32_t)hx | ((uint32_t)hy << 16);
    lo = (uint32_t)lx | ((uint32_t)ly << 16);
}

__device__ __forceinline__ void mma_bf16(float* d, const uint32_t* a, const uint32_t* b) {
    asm volatile(
        "mma.sync.aligned.m16n8k16.row.col.f32.bf16.bf16.f32 "
        "{%0,%1,%2,%3}, {%4,%5,%6,%7}, {%8,%9}, {%0,%1,%2,%3};\n"
        : "+f"(d[0]), "+f"(d[1]), "+f"(d[2]), "+f"(d[3])
        : "r"(a[0]), "r"(a[1]), "r"(a[2]), "r"(a[3]), "r"(b[0]), "r"(b[1]));
}

__device__ __forceinline__ void ldsm4(uint32_t* r, const uint32_t* p) {
    uint32_t a = (uint32_t)__cvta_generic_to_shared(p);
    asm volatile("ldmatrix.sync.aligned.m8n8.x4.shared.b16 {%0,%1,%2,%3}, [%4];"
                 : "=r"(r[0]), "=r"(r[1]), "=r"(r[2]), "=r"(r[3]) : "r"(a));
}

// ---------------- small kernels ---------------------------------------------
__global__ void k_prep() {
    int i = blockIdx.x * blockDim.x + threadIdx.x;
    if (i < NN) {
        g_odeg[i] = 0;
        g_ideg[i] = 0;
    }
}

__global__ void k_degree(const int* __restrict__ src, const int* __restrict__ dst) {
    int e = blockIdx.x * blockDim.x + threadIdx.x;
    if (e < EE) {
        atomicAdd(&g_odeg[src[e]], 1);
        atomicAdd(&g_ideg[dst[e]], 1);
    }
}

__global__ void k_norm() {
    int i = blockIdx.x * blockDim.x + threadIdx.x;
    if (i < NN) {
        g_nsrc[i] = rsqrtf(fmaxf((float)g_odeg[i], 1.0f));
        g_ndst[i] = rsqrtf(fmaxf((float)g_ideg[i], 1.0f));
    }
    if (blockIdx.x == 0 && threadIdx.x < HH) {
        g_psum[threadIdx.x] = 0.0f;
        g_pmax[threadIdx.x] = -INFINITY;
    }
}

// ---------------- CSR build ---------------------------------------------------
__global__ void k_scan1() {
    __shared__ int sh[256];
    int t = threadIdx.x;
    int i = blockIdx.x * 256 + t;
    int v = (i < NN) ? g_ideg[i] : 0;
    sh[t] = v;
    __syncthreads();
    #pragma unroll
    for (int off = 1; off < 256; off <<= 1) {
        int add = (t >= off) ? sh[t - off] : 0;
        __syncthreads();
        sh[t] += add;
        __syncthreads();
    }
    if (i < NN) g_rowstart[i] = sh[t] - v;
    if (t == 255) g_blksum[blockIdx.x] = sh[255];
}

__global__ void k_scan2(int nblk) {
    __shared__ int sh[512];
    int t = threadIdx.x;
    int v = (t < nblk) ? g_blksum[t] : 0;
    sh[t] = v;
    __syncthreads();
    #pragma unroll
    for (int off = 1; off < 512; off <<= 1) {
        int add = (t >= off) ? sh[t - off] : 0;
        __syncthreads();
        sh[t] += add;
        __syncthreads();
    }
    if (t < nblk) g_blksum[t] = sh[t] - v;
}

__global__ void k_scan3() {
    int i = blockIdx.x * blockDim.x + threadIdx.x;
    if (i < NN) {
        g_rowstart[i] += g_blksum[i >> 8];
        g_cursor[i] = 0;
    }
    if (i == 0) g_rowstart[NN] = EE;
}

__global__ void k_csr_fill(const int* __restrict__ src, const int* __restrict__ dst) {
    int e = blockIdx.x * blockDim.x + threadIdx.x;
    if (e < EE) {
        int d = dst[e];
        int pos = atomicAdd(&g_cursor[d], 1);
        g_csr_src[g_rowstart[d] + pos] = src[e];
    }
}

// ---------------- tensor-core GEMM (bf16x3, m16n8k16, double-buffered) -------
// C[N,256] = (A[N,K] * norm[row]) @ W[K,256]
// BM=128, BN=128, BK=16, 8 warps, warp tile 64(m) x 32(n).
// Double-buffered smem: ONE __syncthreads per k-tile; loads overlap compute.
template <int K>
__global__ void __launch_bounds__(256, 2)
k_gemm_tc(const float* __restrict__ A, const float* __restrict__ W,
          const float* __restrict__ norm, float* __restrict__ C) {
    __shared__ __align__(16) uint32_t Ah[2][128][12];
    __shared__ __align__(16) uint32_t Al[2][128][12];
    __shared__ __align__(16) uint32_t Bh[2][8][136];
    __shared__ __align__(16) uint32_t Bl[2][8][136];

    const int tid  = threadIdx.x;
    const int lane = tid & 31;
    const int wid  = tid >> 5;
    const int wm   = wid & 1;        // m block of 64
    const int wn   = wid >> 1;       // n block of 32
    const int m0   = blockIdx.y * 128;
    const int n0   = blockIdx.x * 128;

    const int a_r0 = tid >> 2;
    const int a_r1 = a_r0 + 64;
    const int a_c  = (tid & 3) << 2;
    const int a_k2 = (tid & 3) << 1;
    const int kb_e = (tid >> 5) << 1;
    const int b_k2 = tid >> 5;
    const int b_c  = (tid & 31) << 2;

    const float nrm0 = (m0 + a_r0 < NN) ? norm[m0 + a_r0] : 0.f;
    const float nrm1 = (m0 + a_r1 < NN) ? norm[m0 + a_r1] : 0.f;

    const int lm_r = (lane & 7) + ((lane >> 3) & 1) * 8;   // 0..15
    const int lm_c = (lane >> 4) * 4;                      // 0 or 4
    const int g    = lane >> 2;
    const int tig  = lane & 3;

    float acc[4][4][4];
    #pragma unroll
    for (int mt = 0; mt < 4; mt++)
        #pragma unroll
        for (int nt = 0; nt < 4; nt++)
            #pragma unroll
            for (int i = 0; i < 4; i++) acc[mt][nt][i] = 0.f;

    float4 pa0, pa1, pb0, pb1;

    #define LOAD_TILE(kt)                                                         \
        {                                                                         \
            int kbase = (kt) * 16;                                                \
            pa0 = (m0 + a_r0 < NN)                                                \
                ? *(const float4*)(A + (size_t)(m0 + a_r0) * K + kbase + a_c)     \
                : make_float4(0.f, 0.f, 0.f, 0.f);                                \
            pa1 = (m0 + a_r1 < NN)                                                \
                ? *(const float4*)(A + (size_t)(m0 + a_r1) * K + kbase + a_c)     \
                : make_float4(0.f, 0.f, 0.f, 0.f);                                \
            pb0 = *(const float4*)(W + (size_t)(kbase + kb_e) * HH + n0 + b_c);   \
            pb1 = *(const float4*)(W + (size_t)(kbase + kb_e + 1) * HH + n0 + b_c); \
        }

    #define STORE_TILE(buf)                                                       \
        {                                                                         \
            uint32_t h01, l01, h23, l23;                                          \
            bf16x3_pack(pa0.x * nrm0, pa0.y * nrm0, h01, l01);                    \
            bf16x3_pack(pa0.z * nrm0, pa0.w * nrm0, h23, l23);                    \
            *(uint2*)&Ah[buf][a_r0][a_k2] = make_uint2(h01, h23);                 \
            *(uint2*)&Al[buf][a_r0][a_k2] = make_uint2(l01, l23);                 \
            bf16x3_pack(pa1.x * nrm1, pa1.y * nrm1, h01, l01);                    \
            bf16x3_pack(pa1.z * nrm1, pa1.w * nrm1, h23, l23);                    \
            *(uint2*)&Ah[buf][a_r1][a_k2] = make_uint2(h01, h23);                 \
            *(uint2*)&Al[buf][a_r1][a_k2] = make_uint2(l01, l23);                 \
            uint32_t bh0, bl0, bh1, bl1, bh2, bl2, bh3, bl3;                      \
            bf16x3_pack(pb0.x, pb1.x, bh0, bl0);                                  \
            bf16x3_pack(pb0.y, pb1.y, bh1, bl1);                                  \
            bf16x3_pack(pb0.z, pb1.z, bh2, bl2);                                  \
            bf16x3_pack(pb0.w, pb1.w, bh3, bl3);                                  \
            *(uint4*)&Bh[buf][b_k2][b_c] = make_uint4(bh0, bh1, bh2, bh3);        \
            *(uint4*)&Bl[buf][b_k2][b_c] = make_uint4(bl0, bl1, bl2, bl3);        \
        }

    constexpr int KT = K / 16;

    LOAD_TILE(0);
    STORE_TILE(0);
    __syncthreads();

    for (int kt = 0; kt < KT; kt++) {
        const int cur = kt & 1;
        const int alt = cur ^ 1;

        // prefetch next tile into registers (overlaps with mma below)
        if (kt + 1 < KT) LOAD_TILE(kt + 1);

        uint32_t ah[4][4];
        #pragma unroll
        for (int mt = 0; mt < 4; mt++)
            ldsm4(ah[mt], &Ah[cur][wm * 64 + mt * 16 + lm_r][lm_c]);

        uint32_t bh[4][2];
        #pragma unroll
        for (int nt = 0; nt < 4; nt++) {
            int nb = wn * 32 + nt * 8 + g;
            bh[nt][0] = Bh[cur][tig][nb];
            bh[nt][1] = Bh[cur][tig + 4][nb];
        }
        #pragma unroll
        for (int mt = 0; mt < 4; mt++)
            #pragma unroll
            for (int nt = 0; nt < 4; nt++)
                mma_bf16(acc[mt][nt], ah[mt], bh[nt]);

        uint32_t bl[4][2];
        #pragma unroll
        for (int nt = 0; nt < 4; nt++) {
            int nb = wn * 32 + nt * 8 + g;
            bl[nt][0] = Bl[cur][tig][nb];
            bl[nt][1] = Bl[cur][tig + 4][nb];
        }
        #pragma unroll
        for (int mt = 0; mt < 4; mt++)
            #pragma unroll
            for (int nt = 0; nt < 4; nt++)
                mma_bf16(acc[mt][nt], ah[mt], bl[nt]);

        uint32_t al[4][4];
        #pragma unroll
        for (int mt = 0; mt < 4; mt++)
            ldsm4(al[mt], &Al[cur][wm * 64 + mt * 16 + lm_r][lm_c]);
        #pragma unroll
        for (int mt = 0; mt < 4; mt++)
            #pragma unroll
            for (int nt = 0; nt < 4; nt++)
                mma_bf16(acc[mt][nt], al[mt], bh[nt]);

        // store prefetched tile into the alternate buffer, then ONE sync
        if (kt + 1 < KT) STORE_TILE(alt);
        __syncthreads();
    }

    #pragma unroll
    for (int mt = 0; mt < 4; mt++) {
        #pragma unroll
        for (int nt = 0; nt < 4; nt++) {
            int row = m0 + wm * 64 + mt * 16 + g;
            int col = n0 + wn * 32 + nt * 8 + tig * 2;
            if (row < NN)
                *(float2*)(C + (size_t)row * HH + col) =
                    make_float2(acc[mt][nt][0], acc[mt][nt][1]);
            if (row + 8 < NN)
                *(float2*)(C + (size_t)(row + 8) * HH + col) =
                    make_float2(acc[mt][nt][2], acc[mt][nt][3]);
        }
    }
    #undef LOAD_TILE
    #undef STORE_TILE
}

// ---------------- CSR gather: full row, 1 LDG.256 per lane per edge ----------
// O[n] = leaky( (sum_{e in in(n)} X[src[e]]) * ndst[n] + bias )
// One warp per node. Lane covers floats [lane*8, lane*8+8) of the 256-wide row,
// so 32 lanes = whole row with ONE 256-bit load per lane per edge.
template <bool POOL>
__global__ void __launch_bounds__(256)
k_gather(const float* __restrict__ X, float* __restrict__ O,
         const float* __restrict__ ndst, const float* __restrict__ bias) {
    __shared__ int   s_idx[8][128];
    __shared__ float s_sum[HH];
    __shared__ float s_max[HH];

    const int lane = threadIdx.x & 31;
    const int wip  = threadIdx.x >> 5;
    const int n    = (blockIdx.x * blockDim.x + threadIdx.x) >> 5;

    if (POOL) {
        s_sum[threadIdx.x] = 0.0f;
        s_max[threadIdx.x] = -INFINITY;
        __syncthreads();
    }

    const int fcol = lane * 8;
    f8 a = {0.f, 0.f, 0.f, 0.f, 0.f, 0.f, 0.f, 0.f};

    const bool valid = (n < NN);
    float o[8];
    if (valid) {
        const int beg = g_rowstart[n];
        const int cnt = g_rowstart[n + 1] - beg;

        for (int base = 0; base < cnt; base += 128) {
            const int chunk = min(128, cnt - base);
            for (int j = lane; j < chunk; j += 32)
                s_idx[wip][j] = __ldg(&g_csr_src[beg + base + j]);
            __syncwarp();

            int j = 0;
            for (; j + 4 <= chunk; j += 4) {
                int e0 = s_idx[wip][j + 0];
                int e1 = s_idx[wip][j + 1];
                int e2 = s_idx[wip][j + 2];
                int e3 = s_idx[wip][j + 3];
                f8 v0 = ldg256(X + (size_t)e0 * HH + fcol);
                f8 v1 = ldg256(X + (size_t)e1 * HH + fcol);
                f8 v2 = ldg256(X + (size_t)e2 * HH + fcol);
                f8 v3 = ldg256(X + (size_t)e3 * HH + fcol);
                f8acc(a, v0); f8acc(a, v1); f8acc(a, v2); f8acc(a, v3);
            }
            for (; j < chunk; j++) {
                int e0 = s_idx[wip][j];
                f8 v0 = ldg256(X + (size_t)e0 * HH + fcol);
                f8acc(a, v0);
            }
            __syncwarp();
        }

        const float nd = ndst[n];
        #pragma unroll
        for (int i = 0; i < 8; i++) {
            float bb = __ldg(&bias[fcol + i]);
            o[i] = leaky(fmaf((&a.a0)[i], nd, bb));
        }
        float4 o0 = make_float4(o[0], o[1], o[2], o[3]);
        float4 o1 = make_float4(o[4], o[5], o[6], o[7]);
        __stcs((float4*)(O + (size_t)n * HH + fcol), o0);
        __stcs((float4*)(O + (size_t)n * HH + fcol + 4), o1);
    }

    if (POOL) {
        if (valid) {
            #pragma unroll
            for (int i = 0; i < 8; i++) {
                atomicAdd(&s_sum[fcol + i], o[i]);
                atomicMaxFloat(&s_max[fcol + i], o[i]);
            }
        }
        __syncthreads();
        atomicAdd(&g_psum[threadIdx.x], s_sum[threadIdx.x]);
        atomicMaxFloat(&g_pmax[threadIdx.x], s_max[threadIdx.x]);
    }
}

// ---------------- generator head ---------------------------------------------
__global__ void k_final(const float* __restrict__ B, const int* __restrict__ node_index,
                        const float* __restrict__ b2,
                        const float* __restrict__ Wg, const float* __restrict__ bg,
                        const float* __restrict__ eps, float* __restrict__ out) {
    __shared__ float pooled[768];
    __shared__ float red[256];
    int t  = threadIdx.x;
    int ni = *node_index;

    pooled[t]       = g_psum[t];
    pooled[256 + t] = g_pmax[t];
    pooled[512 + t] = B[(size_t)ni * HH + t];
    __syncthreads();

    float fdv[4];
    #pragma unroll
    for (int o = 0; o < 4; o++) {
        int k = t + o * 256;
        float acc = bg[k];
        for (int i = 0; i < 768; i++)
            acc = fmaf(pooled[i], Wg[(size_t)i * 1024 + k], acc);
        fdv[o] = acc;
    }
    float mu1 = fdv[0],        mu2 = fdv[1];
    float sg1 = fabsf(fdv[2]), sg2 = fabsf(fdv[3]);
    float e1 = eps[t], e2 = eps[t + 256];
    float fn1 = fmaf(sg1, e1, mu1);
    float fn2 = fmaf(sg2, e2, mu2);

    out[t]              = fn1;  out[t + 256]        = fn2;
    out[512 + t]        = mu1;  out[512 + t + 256]  = mu2;
    out[1024 + t]       = sg1;  out[1024 + t + 256] = sg2;

    const float HALF_LOG_2PI = 0.9189385332046727f;
    float r1 = (fn1 - mu1) / sg1;
    float r2 = (fn2 - mu2) / sg2;
    float lp = (-0.5f * r1 * r1 - logf(sg1) - HALF_LOG_2PI)
             + (-0.5f * r2 * r2 - logf(sg2) - HALF_LOG_2PI);
    red[t] = lp;
    __syncthreads();
    for (int off = 128; off > 0; off >>= 1) {
        if (t < off) red[t] += red[t + off];
        __syncthreads();
    }
    if (t == 0) out[1536] = red[0] / 512.0f;
}

// ---------------- launcher ----------------------------------------------------
extern "C" void kernel_launch(void* const* d_in, const int* in_sizes, int n_in,
                              void* d_out, int out_size) {
    const float* feat = (const float*)d_in[0];
    const int*   src  = (const int*)d_in[1];
    const int*   dst  = (const int*)d_in[2];
    const int*   nidx = (const int*)d_in[3];
    const float* W1   = (const float*)d_in[4];
    const float* b1   = (const float*)d_in[5];
    const float* W2   = (const float*)d_in[6];
    const float* b2   = (const float*)d_in[7];
    const float* Wg   = (const float*)d_in[8];
    const float* bg   = (const float*)d_in[9];
    const float* eps  = (const float*)d_in[10];
    float* out = (float*)d_out;

    void *p0, *p1, *p2, *pns, *pnd;
    cudaGetSymbolAddress(&p0, g_B0);
    cudaGetSymbolAddress(&p1, g_B1);
    cudaGetSymbolAddress(&p2, g_B2);
    cudaGetSymbolAddress(&pns, g_nsrc);
    cudaGetSymbolAddress(&pnd, g_ndst);
    float* B0 = (float*)p0;
    float* B1 = (float*)p1;
    float* B2 = (float*)p2;
    float* nsrc = (float*)pns;
    float* ndst = (float*)pnd;

    const int DEG_BLKS  = (EE + 255) / 256;
    const int N_BLKS    = (NN + 255) / 256;      // 391
    const dim3 GEMM_GRID(2, (NN + 127) / 128);   // 782 m-tiles x 2 n-tiles
    const int GATH_BLKS = (NN + 7) / 8;          // one warp per node

    // launch order: stream index 3 (the ncu-profiled slot) is gemm1
    k_prep<<<N_BLKS, 256>>>();                                   // 0
    k_degree<<<DEG_BLKS, 256>>>(src, dst);                       // 1
    k_norm<<<N_BLKS, 256>>>();                                   // 2
    k_gemm_tc<FF><<<GEMM_GRID, 256>>>(feat, W1, nsrc, B0);       // 3  <- profiled
    k_scan1<<<N_BLKS, 256>>>();                                  // 4
    k_scan2<<<1, 512>>>(N_BLKS);                                 // 5
    k_scan3<<<N_BLKS, 256>>>();                                  // 6
    k_csr_fill<<<DEG_BLKS, 256>>>(src, dst);                     // 7

    // layer 1: gather (full row per warp)
    k_gather<false><<<GATH_BLKS, 256>>>(B0, B1, ndst, b1);       // 8

    // layer 2
    k_gemm_tc<HH><<<GEMM_GRID, 256>>>(B1, W2, nsrc, B2);         // 9
    k_gather<true><<<GATH_BLKS, 256>>>(B2, B0, ndst, b2);        // 10

    // head
    k_final<<<1, 256>>>(B0, nidx, b2, Wg, bg, eps, out);         // 11
}